// round 11
// baseline (speedup 1.0000x reference)
#include <cuda_runtime.h>
#include <math.h>

#define Bz   4
#define Sq   4096
#define Hn   8
#define Dn   64
#define LNE  512          // H*D
#define TS   8            // tokens per GEMM tile == scan tile
#define NT   512          // Sq/TS
#define GN   16           // scan groups
#define GT   32           // tiles per group (GN*GT == NT)
#define RK   132          // row-major A stride (128 k + 4 pad); A-frag LDS conflict-free
#define FS   68           // Fs/Is stride
#define WS1  200          // W plane stride: bank = 8t+g -> conflict-free B-frag loads

// gemm1 dynamic smem layout (floats):
//   [0, 8704)        As (64*132 used) / later Fs|Is (2*64*68 = 8704)
//   [8704, 11904)    W stage 0: hi[8*200], lo[8*200]
//   [11904, 15104)   W stage 1
#define SB_FLOATS 15104
#define SB_BYTES  (SB_FLOATS*4)

// ---- scratch (allocation-free: __device__ globals) ----
__device__ float g_fg  [(size_t)Bz*Sq*LNE];
__device__ float g_igh [(size_t)Bz*Sq*LNE];
__device__ float g_tsum[(size_t)Bz*NT*LNE];
__device__ float g_toff[(size_t)Bz*NT*LNE];
__device__ float g_gsum[(size_t)Bz*GN*LNE];
__device__ float g_tA  [(size_t)Bz*NT*LNE];
__device__ float g_tB  [(size_t)Bz*NT*LNE];
__device__ float g_cIn [(size_t)Bz*NT*LNE];
__device__ float g_gA  [(size_t)Bz*GN*LNE];
__device__ float g_gB  [(size_t)Bz*GN*LNE];
__device__ float g_whi [128*192];
__device__ float g_wlo [128*192];

// sigmoid via HW tanh
__device__ __forceinline__ float sigm(float x){
    float t;
    asm("tanh.approx.f32 %0, %1;" : "=f"(t) : "f"(x*0.5f));
    return fmaf(t, 0.5f, 0.5f);
}

// ---- packed f32x2 helpers (for gemm2, unchanged) ----
__device__ __forceinline__ unsigned long long pk2(float x, float y){
    unsigned long long r;
    asm("mov.b64 %0, {%1,%2};" : "=l"(r) : "f"(x), "f"(y));
    return r;
}
__device__ __forceinline__ void fma2(unsigned long long &d, unsigned long long a, unsigned long long b){
    asm("fma.rn.f32x2 %0, %1, %2, %3;" : "=l"(d) : "l"(a), "l"(b), "l"(d));
}
__device__ __forceinline__ float2 up2(unsigned long long v){
    float2 f;
    asm("mov.b64 {%0,%1}, %2;" : "=f"(f.x), "=f"(f.y) : "l"(v));
    return f;
}

// ---- tf32 helpers ----
__device__ __forceinline__ unsigned tf32r(float x){
    unsigned r;
    asm("cvt.rna.tf32.f32 %0, %1;" : "=r"(r) : "f"(x));
    return r;
}
__device__ __forceinline__ void mma8(float* c, const unsigned* a, unsigned b0, unsigned b1){
    asm volatile("mma.sync.aligned.m16n8k8.row.col.f32.tf32.tf32.f32 "
        "{%0,%1,%2,%3}, {%4,%5,%6,%7}, {%8,%9}, {%0,%1,%2,%3};"
        : "+f"(c[0]), "+f"(c[1]), "+f"(c[2]), "+f"(c[3])
        : "r"(a[0]), "r"(a[1]), "r"(a[2]), "r"(a[3]), "r"(b0), "r"(b1));
}

// ---- cp.async helpers ----
__device__ __forceinline__ unsigned su32(const void* p){
    return (unsigned)__cvta_generic_to_shared(p);
}
__device__ __forceinline__ void cp16(unsigned dst, const void* src){
    asm volatile("cp.async.ca.shared.global [%0], [%1], 16;" :: "r"(dst), "l"(src));
}
__device__ __forceinline__ void cpcommit(){
    asm volatile("cp.async.commit_group;");
}
template<int N> __device__ __forceinline__ void cpwait(){
    asm volatile("cp.async.wait_group %0;" :: "n"(N));
}

// ============ W hi/lo tf32 split (once per launch, ~2us) ============
__global__ void k_wsplit(const float* __restrict__ Wh){
    int i = blockIdx.x*512 + threadIdx.x;
    if(i < 128*192){
        float w = Wh[i];
        unsigned hb = tf32r(w);
        float hf = __uint_as_float(hb);
        g_whi[i] = hf;
        g_wlo[i] = __uint_as_float(tf32r(w - hf));
    }
}

// ============ cumsum chunked scan (exclusive, along S) ============
__global__ void k_tilesum(const float* __restrict__ x){
    int blk = blockIdx.x;
    int b = blk >> 9, t = blk & 511;
    int lane = threadIdx.x;
    const float* p = x + ((size_t)(b*Sq + t*TS))*LNE + lane;
    float s = 0.f;
    #pragma unroll
    for(int i=0;i<TS;i++) s += p[(size_t)i*LNE];
    g_tsum[(size_t)blk*LNE + lane] = s;
}

__global__ void k_gsum(){
    int blk = blockIdx.x;
    int b = blk >> 4, g = blk & 15;
    int lane = threadIdx.x;
    size_t base = ((size_t)b*NT + g*GT)*LNE + lane;
    float s = 0.f;
    #pragma unroll
    for(int i=0;i<GT;i++) s += g_tsum[base + (size_t)i*LNE];
    g_gsum[(size_t)blk*LNE + lane] = s;
}

__global__ void k_tscan(){
    int blk = blockIdx.x;
    int b = blk >> 4, g = blk & 15;
    int lane = threadIdx.x;
    float run = 0.f;
    size_t gbase = ((size_t)b*GN)*LNE + lane;
    for(int i=0;i<g;i++) run += g_gsum[gbase + (size_t)i*LNE];
    size_t base = ((size_t)b*NT + g*GT)*LNE + lane;
    float v[GT];
    #pragma unroll
    for(int i=0;i<GT;i++) v[i] = g_tsum[base + (size_t)i*LNE];
    #pragma unroll
    for(int i=0;i<GT;i++){ g_toff[base + (size_t)i*LNE] = run; run += v[i]; }
}

// ============ LN + GEMM1 (tf32 mma) + gates + lgate tile partials ============
// 128 threads = 4 warps; warp w owns rows 16w..16w+15.
// mma m16n8k8: g = lane>>2, t = lane&3.
#define W1N 16           // 16 chunks of 8 k-rows (one k-tile each)
__global__ __launch_bounds__(128, 2) void k_ln_gemm1(
    const float* __restrict__ x,  const float* __restrict__ bh,
    const float* __restrict__ gamma, const float* __restrict__ beta)
{
    extern __shared__ __align__(16) float smem[];
    float* As = smem;                   // 64*RK floats
    float* Wst[2] = { smem + 8704, smem + 11904 };  // each: hi[1600] | lo[1600]
    __shared__ float redS[4][TS], redQ[4][TS];
    __shared__ float s_mean[TS], s_rstd[TS];

    int blk = blockIdx.x;
    int b = blk >> 9, t8 = blk & 511;
    int tid = threadIdx.x;
    int s0 = t8*TS;

    // G0: x tile -> As[r][k] via cp.async
    const float4* xin = reinterpret_cast<const float4*>(x + ((size_t)(b*Sq + s0))*LNE);
    #pragma unroll
    for(int q=0;q<8;q++){
        int i = tid + q*128;
        int lin = i*4;
        int s = lin >> 9, lam = lin & 511, h = lam >> 6, k = lam & 63;
        cp16(su32(&As[(s*8+h)*RK + k]), xin + i);
    }
    cpcommit();
    // G1: W chunk 0 (hi+lo planes, 384 float4 each, 3/thread per plane)
    {
        const float4* hsrc = reinterpret_cast<const float4*>(g_whi);
        const float4* lsrc = reinterpret_cast<const float4*>(g_wlo);
        #pragma unroll
        for(int j=0;j<3;j++){
            int id = tid + j*128;            // 0..383
            int rr = id/48, jj = id%48;
            cp16(su32(Wst[0] +        rr*WS1 + jj*4), hsrc + id);
            cp16(su32(Wst[0] + 1600 + rr*WS1 + jj*4), lsrc + id);
        }
    }
    cpcommit();
    cpwait<1>();
    __syncthreads();

    // exclusive cumsum in registers + fused LN stats
    float cs[4][TS];
    float psum[TS], psq[TS];
    #pragma unroll
    for(int s=0;s<TS;s++){ psum[s]=0.f; psq[s]=0.f; }
    #pragma unroll
    for(int q=0;q<4;q++){
        int lam = tid + q*128;
        int h = lam >> 6, k = lam & 63;
        float run = g_toff[((size_t)(b*NT + t8))*LNE + lam];
        #pragma unroll
        for(int s=0;s<TS;s++){
            float xv = As[(s*8+h)*RK + k];
            cs[q][s] = run;
            psum[s] += run;
            psq[s]  += run*run;
            run += xv;
        }
    }
    #pragma unroll
    for(int o=16;o>0;o>>=1){
        #pragma unroll
        for(int s=0;s<TS;s++){
            psum[s] += __shfl_xor_sync(0xffffffffu, psum[s], o);
            psq[s]  += __shfl_xor_sync(0xffffffffu, psq[s],  o);
        }
    }
    {
        int w = tid >> 5, lanei = tid & 31;
        if(lanei==0){
            #pragma unroll
            for(int s=0;s<TS;s++){ redS[w][s] = psum[s]; redQ[w][s] = psq[s]; }
        }
    }
    __syncthreads();
    if(tid < TS){
        float sum = redS[0][tid] + redS[1][tid] + redS[2][tid] + redS[3][tid];
        float sq  = redQ[0][tid] + redQ[1][tid] + redQ[2][tid] + redQ[3][tid];
        float m = sum * (1.f/512.f);
        float var = sq * (1.f/512.f) - m*m;
        s_mean[tid] = m;
        s_rstd[tid] = rsqrtf(var + 1e-5f);
    }
    __syncthreads();

    // write normalized csum -> As[r][64+k]
    #pragma unroll
    for(int q=0;q<4;q++){
        int lam = tid + q*128;
        int h = lam >> 6, k = lam & 63;
        float ga = gamma[lam], be = beta[lam];
        #pragma unroll
        for(int s=0;s<TS;s++){
            As[(s*8+h)*RK + 64 + k] =
                (cs[q][s] - s_mean[s]) * s_rstd[s] * ga + be;
        }
    }

    // ===== tf32 mma mainloop =====
    int lane = tid & 31, wq = tid >> 5;
    int g = lane >> 2, t = lane & 3;
    int rb = wq*16;
    float acc[24][4];
    #pragma unroll
    for(int nt=0;nt<24;nt++)
        #pragma unroll
        for(int e=0;e<4;e++) acc[nt][e] = 0.f;

    for(int c=0;c<W1N;c++){
        cpwait<0>();
        __syncthreads();
        if(c+1 < W1N){
            const float4* hsrc = reinterpret_cast<const float4*>(g_whi + (c+1)*8*192);
            const float4* lsrc = reinterpret_cast<const float4*>(g_wlo + (c+1)*8*192);
            float* dst = Wst[(c+1)&1];
            #pragma unroll
            for(int j=0;j<3;j++){
                int id = tid + j*128;
                int rr = id/48, jj = id%48;
                cp16(su32(dst +        rr*WS1 + jj*4), hsrc + id);
                cp16(su32(dst + 1600 + rr*WS1 + jj*4), lsrc + id);
            }
        }
        cpcommit();

        int k0 = c*8;
        // A fragments (hi/lo split at load)
        float ar[4];
        ar[0] = As[(rb+g  )*RK + k0 + t    ];
        ar[1] = As[(rb+g+8)*RK + k0 + t    ];
        ar[2] = As[(rb+g  )*RK + k0 + t + 4];
        ar[3] = As[(rb+g+8)*RK + k0 + t + 4];
        unsigned ah[4], al[4];
        #pragma unroll
        for(int e=0;e<4;e++){
            ah[e] = tf32r(ar[e]);
            al[e] = tf32r(ar[e] - __uint_as_float(ah[e]));
        }

        const float* whc = Wst[c&1];
        const float* wlc = whc + 1600;
        #pragma unroll
        for(int nt=0;nt<24;nt++){
            int n = nt*8 + g;
            unsigned bh0 = __float_as_uint(whc[ t   *WS1 + n]);
            unsigned bh1 = __float_as_uint(whc[(t+4)*WS1 + n]);
            unsigned bl0 = __float_as_uint(wlc[ t   *WS1 + n]);
            unsigned bl1 = __float_as_uint(wlc[(t+4)*WS1 + n]);
            mma8(acc[nt], ah, bh0, bh1);
            mma8(acc[nt], ah, bl0, bl1);
            mma8(acc[nt], al, bh0, bh1);
        }
    }
    __syncthreads();   // done with As; smem becomes Fs|Is

    float* Fs = smem;            // [64][FS]
    float* Is = smem + 64*FS;

    // gates: thread owns rows {rb+g, rb+g+8}, cols {8nt+2t, +1}; triples via nt/nt+8/nt+16
    #pragma unroll
    for(int nt=0;nt<8;nt++){
        int j = nt*8 + 2*t;
        float2 bi  = *reinterpret_cast<const float2*>(&bh[j]);
        float2 bf  = *reinterpret_cast<const float2*>(&bh[64+j]);
        float2 bhd = *reinterpret_cast<const float2*>(&bh[128+j]);
        #pragma unroll
        for(int half=0;half<2;half++){
            int r = rb + g + half*8;
            int s = r >> 3, h = r & 7;
            float ig0 = acc[nt   ][half*2+0] + bi.x;
            float ig1 = acc[nt   ][half*2+1] + bi.y;
            float fr0 = acc[nt+8 ][half*2+0] + bf.x;
            float fr1 = acc[nt+8 ][half*2+1] + bf.y;
            float hd0 = acc[nt+16][half*2+0] + bhd.x;
            float hd1 = acc[nt+16][half*2+1] + bhd.y;
            float f0 = sigm(fr0), f1 = sigm(fr1);
            float g0 = sigm(ig0)*fmaxf(hd0,0.f);
            float g1 = sigm(ig1)*fmaxf(hd1,0.f);
            size_t gi = ((size_t)(b*Sq + s0 + s))*LNE + h*64 + j;
            *reinterpret_cast<float2*>(&g_fg [gi]) = make_float2(f0,f1);
            *reinterpret_cast<float2*>(&g_igh[gi]) = make_float2(g0,g1);
            *reinterpret_cast<float2*>(&Fs[r*FS + j]) = make_float2(f0,f1);
            *reinterpret_cast<float2*>(&Is[r*FS + j]) = make_float2(g0,g1);
        }
    }
    __syncthreads();

    // per-tile lgate partials
    #pragma unroll
    for(int q=0;q<4;q++){
        int lam = tid + q*128;
        int h = lam >> 6, d = lam & 63;
        float A = 1.f, Bv = 0.f;
        #pragma unroll
        for(int s=0;s<TS;s++){
            int r = s*8 + h;
            float f = Fs[r*FS + d];
            float v = Is[r*FS + d];
            Bv = Bv*f + v;
            A *= f;
        }
        size_t ti = ((size_t)(b*NT + t8))*LNE + lam;
        g_tA[ti] = A;
        g_tB[ti] = Bv;
    }
}

// ============ cell carry scan over tiles ============
__global__ void k_cgsum(){
    int blk = blockIdx.x;
    int b = blk >> 4, g = blk & 15;
    int lane = threadIdx.x;
    size_t base = ((size_t)b*NT + g*GT)*LNE + lane;
    float A = 1.f, Bv = 0.f;
    #pragma unroll
    for(int i=0;i<GT;i++){
        float a = g_tA[base + (size_t)i*LNE];
        float v = g_tB[base + (size_t)i*LNE];
        Bv = Bv*a + v;
        A *= a;
    }
    g_gA[(size_t)blk*LNE + lane] = A;
    g_gB[(size_t)blk*LNE + lane] = Bv;
}

__global__ void k_ctscan(const float* __restrict__ icx){
    int blk = blockIdx.x;
    int b = blk >> 4, g = blk & 15;
    int lane = threadIdx.x;
    float c = icx[lane];
    size_t gbase = ((size_t)b*GN)*LNE + lane;
    for(int i=0;i<g;i++)
        c = g_gA[gbase + (size_t)i*LNE]*c + g_gB[gbase + (size_t)i*LNE];
    size_t base = ((size_t)b*NT + g*GT)*LNE + lane;
    #pragma unroll
    for(int i=0;i<GT;i++){
        g_cIn[base + (size_t)i*LNE] = c;
        c = g_tA[base + (size_t)i*LNE]*c + g_tB[base + (size_t)i*LNE];
    }
}

// ============ GEMM2 (og) + cell recompute + output (FFMA2, unchanged) ============
#define W2C 16
#define W2N 8
__global__ __launch_bounds__(128, 2) void k_gemm2(
    const float* __restrict__ x, const float* __restrict__ Wo,
    const float* __restrict__ bo, float* __restrict__ out)
{
    __shared__ __align__(16) float As[64*RK];
    __shared__ __align__(16) float Wb[2][W2C*64];
    int blk = blockIdx.x;
    int b = blk >> 9, t = blk & 511;
    int tid = threadIdx.x;
    int s0 = t*TS;

    const float4* xin = reinterpret_cast<const float4*>(x + ((size_t)(b*Sq + s0))*LNE);
    #pragma unroll
    for(int q=0;q<8;q++){
        int i = tid + q*128;
        int lin = i*4;
        int s = lin >> 9, lam = lin & 511, h = lam >> 6, k = lam & 63;
        cp16(su32(&As[(s*8+h)*RK + k]), xin + i);
    }
    cpcommit();
    {
        const float4* wsrc = reinterpret_cast<const float4*>(Wo);
        cp16(su32(&Wb[0][tid*4]), wsrc + tid);
        cp16(su32(&Wb[0][(tid+128)*4]), wsrc + tid + 128);
    }
    cpcommit();

    #pragma unroll
    for(int q=0;q<4;q++){
        int lam = tid + q*128;
        int h = lam >> 6, k = lam & 63;
        float c = g_cIn[((size_t)(b*NT + t))*LNE + lam];
        size_t idx = ((size_t)(b*Sq + s0))*LNE + lam;
        #pragma unroll
        for(int s=0;s<TS;s++){
            c = g_fg[idx]*c + g_igh[idx];
            As[(s*8+h)*RK + 64 + k] = c;
            idx += LNE;
        }
    }

    int tx = tid & 15, ty = tid >> 4;
    int r0 = ty*8, c0 = tx*4;
    unsigned long long acc[8][2];
    #pragma unroll
    for(int i=0;i<8;i++){ acc[i][0]=0ull; acc[i][1]=0ull; }

    for(int c=0;c<W2N;c++){
        cpwait<0>();
        __syncthreads();
        if(c+1 < W2N){
            const float4* wsrc = reinterpret_cast<const float4*>(Wo + (c+1)*W2C*64);
            float* dst = Wb[(c+1)&1];
            cp16(su32(dst + tid*4), wsrc + tid);
            cp16(su32(dst + (tid+128)*4), wsrc + tid + 128);
        }
        cpcommit();

        const float* wc = Wb[c&1];
        #pragma unroll
        for(int kq=0;kq<W2C/4;kq++){
            int kl0 = kq*4;
            float4 av[8];
            #pragma unroll
            for(int i=0;i<8;i++)
                av[i] = *reinterpret_cast<const float4*>(&As[(r0+i)*RK + c*W2C + kl0]);
            #pragma unroll
            for(int kk=0;kk<4;kk++){
                int kl = kl0 + kk;
                ulonglong2 w = *reinterpret_cast<const ulonglong2*>(wc + kl*64 + c0);
                unsigned long long aa[8];
                #pragma unroll
                for(int i=0;i<8;i++){
                    float a = (kk==0)?av[i].x:(kk==1)?av[i].y:(kk==2)?av[i].z:av[i].w;
                    aa[i] = pk2(a, a);
                }
                #pragma unroll
                for(int i=0;i<8;i++){
                    fma2(acc[i][0], aa[i], w.x); fma2(acc[i][1], aa[i], w.y);
                }
            }
        }
    }

    float bo4[4];
    #pragma unroll
    for(int j=0;j<4;j++) bo4[j] = bo[c0+j];

    #pragma unroll
    for(int i=0;i<8;i++){
        int r = r0 + i, s = r >> 3, h = r & 7;
        float2 v0 = up2(acc[i][0]), v1 = up2(acc[i][1]);
        float o0 = sigm(v0.x + bo4[0]);
        float o1 = sigm(v0.y + bo4[1]);
        float o2 = sigm(v1.x + bo4[2]);
        float o3 = sigm(v1.y + bo4[3]);
        float4 cv = *reinterpret_cast<const float4*>(&As[r*RK + 64 + c0]);
        float* dst = out + (((size_t)(b*Sq + s0 + s)*Hn + h)*64) + c0;
        *reinterpret_cast<float4*>(dst) =
            make_float4(o0*cv.x, o1*cv.y, o2*cv.z, o3*cv.w);
    }
}

extern "C" void kernel_launch(void* const* d_in, const int* in_sizes, int n_in,
                              void* d_out, int out_size)
{
    const float* x     = (const float*)d_in[0];
    const float* Wh    = (const float*)d_in[1];
    const float* bh    = (const float*)d_in[2];
    const float* Wo    = (const float*)d_in[3];
    const float* bo    = (const float*)d_in[4];
    const float* gamma = (const float*)d_in[5];
    const float* beta  = (const float*)d_in[6];
    const float* icx   = (const float*)d_in[7];
    float* out = (float*)d_out;

    cudaFuncSetAttribute(k_ln_gemm1,
        cudaFuncAttributeMaxDynamicSharedMemorySize, SB_BYTES);

    k_wsplit  <<<48, 512>>>(Wh);
    k_tilesum <<<Bz*NT, 512>>>(x);
    k_gsum    <<<Bz*GN, 512>>>();
    k_tscan   <<<Bz*GN, 512>>>();
    k_ln_gemm1<<<Bz*NT, 128, SB_BYTES>>>(x, bh, gamma, beta);
    k_cgsum   <<<Bz*GN, 512>>>();
    k_ctscan  <<<Bz*GN, 512>>>(icx);
    k_gemm2   <<<Bz*NT, 128>>>(x, Wo, bo, out);
}

// round 12
// speedup vs baseline: 1.0921x; 1.0921x over previous
#include <cuda_runtime.h>
#include <math.h>

#define Bz   4
#define Sq   4096
#define Hn   8
#define Dn   64
#define LNE  512          // H*D
#define TS   8            // tokens per GEMM tile == scan tile
#define NT   512          // Sq/TS
#define GN   16           // scan groups
#define GT   32           // tiles per group (GN*GT == NT)
#define RK   132          // row-major A stride (128 k + 4 pad); A-frag LDS conflict-free
#define FS   68           // Fs/Is stride
#define WLS  100          // per-lane W-frag smem stride (96 used + 4 pad) -> conflict-free

// gemm1 dynamic smem layout (floats):
//   [0, 8704)        As (64*132 used) / later Fs|Is (2*64*68 = 8704)
//   [8704, 11904)    W frag stage 0: 32 lanes * 100
//   [11904, 15104)   W frag stage 1
#define SB_FLOATS 15104
#define SB_BYTES  (SB_FLOATS*4)

// ---- scratch (allocation-free: __device__ globals) ----
__device__ float g_fg  [(size_t)Bz*Sq*LNE];
__device__ float g_igh [(size_t)Bz*Sq*LNE];
__device__ float g_tsum[(size_t)Bz*NT*LNE];
__device__ float g_toff[(size_t)Bz*NT*LNE];
__device__ float g_gsum[(size_t)Bz*GN*LNE];
__device__ float g_tA  [(size_t)Bz*NT*LNE];
__device__ float g_tB  [(size_t)Bz*NT*LNE];
__device__ float g_cIn [(size_t)Bz*NT*LNE];
__device__ float g_gA  [(size_t)Bz*GN*LNE];
__device__ float g_gB  [(size_t)Bz*GN*LNE];
// fragment-ordered W: [chunk c][lane][48 hi | 48 lo], 96 floats per (c,lane)
__device__ float g_wfrag[16*32*96];

// sigmoid via HW tanh
__device__ __forceinline__ float sigm(float x){
    float t;
    asm("tanh.approx.f32 %0, %1;" : "=f"(t) : "f"(x*0.5f));
    return fmaf(t, 0.5f, 0.5f);
}

// ---- packed f32x2 helpers (for gemm2) ----
__device__ __forceinline__ unsigned long long pk2(float x, float y){
    unsigned long long r;
    asm("mov.b64 %0, {%1,%2};" : "=l"(r) : "f"(x), "f"(y));
    return r;
}
__device__ __forceinline__ void fma2(unsigned long long &d, unsigned long long a, unsigned long long b){
    asm("fma.rn.f32x2 %0, %1, %2, %3;" : "=l"(d) : "l"(a), "l"(b), "l"(d));
}
__device__ __forceinline__ float2 up2(unsigned long long v){
    float2 f;
    asm("mov.b64 {%0,%1}, %2;" : "=f"(f.x), "=f"(f.y) : "l"(v));
    return f;
}

// ---- tf32 helpers ----
__device__ __forceinline__ unsigned tf32r(float x){
    unsigned r;
    asm("cvt.rna.tf32.f32 %0, %1;" : "=r"(r) : "f"(x));
    return r;
}
__device__ __forceinline__ void mma8(float* c, const unsigned* a, unsigned b0, unsigned b1){
    asm volatile("mma.sync.aligned.m16n8k8.row.col.f32.tf32.tf32.f32 "
        "{%0,%1,%2,%3}, {%4,%5,%6,%7}, {%8,%9}, {%0,%1,%2,%3};"
        : "+f"(c[0]), "+f"(c[1]), "+f"(c[2]), "+f"(c[3])
        : "r"(a[0]), "r"(a[1]), "r"(a[2]), "r"(a[3]), "r"(b0), "r"(b1));
}

// ---- cp.async helpers ----
__device__ __forceinline__ unsigned su32(const void* p){
    return (unsigned)__cvta_generic_to_shared(p);
}
__device__ __forceinline__ void cp16(unsigned dst, const void* src){
    asm volatile("cp.async.ca.shared.global [%0], [%1], 16;" :: "r"(dst), "l"(src));
}
__device__ __forceinline__ void cpcommit(){
    asm volatile("cp.async.commit_group;");
}
template<int N> __device__ __forceinline__ void cpwait(){
    asm volatile("cp.async.wait_group %0;" :: "n"(N));
}

// ============ W tf32 hi/lo split into FRAGMENT ORDER ============
// entry id = (c, lane, nt): writes the (b0,b1) pair for that mma fragment.
// b0 = W[c*8 + t][nt*8 + g], b1 = W[c*8 + t + 4][nt*8 + g], lane = (g<<2)|t.
__global__ void k_wsplit(const float* __restrict__ Wh){
    int id = blockIdx.x*512 + threadIdx.x;       // 24 blocks * 512 = 12288 exact
    int c = id / 768;
    int rem = id % 768;
    int lane = rem / 24;
    int nt = rem % 24;
    int g = lane >> 2, t = lane & 3;
    float w0 = Wh[(c*8 + t    )*192 + nt*8 + g];
    float w1 = Wh[(c*8 + t + 4)*192 + nt*8 + g];
    unsigned h0 = tf32r(w0), h1 = tf32r(w1);
    float hf0 = __uint_as_float(h0), hf1 = __uint_as_float(h1);
    float* base = g_wfrag + ((size_t)c*32 + lane)*96 + nt*2;
    base[0]  = hf0;
    base[1]  = hf1;
    base[48] = __uint_as_float(tf32r(w0 - hf0));
    base[49] = __uint_as_float(tf32r(w1 - hf1));
}

// ============ cumsum chunked scan (exclusive, along S) ============
__global__ void k_tilesum(const float* __restrict__ x){
    int blk = blockIdx.x;
    int b = blk >> 9, t = blk & 511;
    int lane = threadIdx.x;
    const float* p = x + ((size_t)(b*Sq + t*TS))*LNE + lane;
    float s = 0.f;
    #pragma unroll
    for(int i=0;i<TS;i++) s += p[(size_t)i*LNE];
    g_tsum[(size_t)blk*LNE + lane] = s;
}

__global__ void k_gsum(){
    int blk = blockIdx.x;
    int b = blk >> 4, g = blk & 15;
    int lane = threadIdx.x;
    size_t base = ((size_t)b*NT + g*GT)*LNE + lane;
    float s = 0.f;
    #pragma unroll
    for(int i=0;i<GT;i++) s += g_tsum[base + (size_t)i*LNE];
    g_gsum[(size_t)blk*LNE + lane] = s;
}

__global__ void k_tscan(){
    int blk = blockIdx.x;
    int b = blk >> 4, g = blk & 15;
    int lane = threadIdx.x;
    float run = 0.f;
    size_t gbase = ((size_t)b*GN)*LNE + lane;
    for(int i=0;i<g;i++) run += g_gsum[gbase + (size_t)i*LNE];
    size_t base = ((size_t)b*NT + g*GT)*LNE + lane;
    float v[GT];
    #pragma unroll
    for(int i=0;i<GT;i++) v[i] = g_tsum[base + (size_t)i*LNE];
    #pragma unroll
    for(int i=0;i<GT;i++){ g_toff[base + (size_t)i*LNE] = run; run += v[i]; }
}

// ============ LN + GEMM1 (tf32 mma, frag-ordered W) ============
#define W1N 16           // 16 chunks of 8 k-rows
__global__ __launch_bounds__(128, 2) void k_ln_gemm1(
    const float* __restrict__ x,  const float* __restrict__ bh,
    const float* __restrict__ gamma, const float* __restrict__ beta)
{
    extern __shared__ __align__(16) float smem[];
    float* As = smem;                   // 64*RK floats
    float* Wst[2] = { smem + 8704, smem + 11904 };  // 32 lanes * WLS each
    __shared__ float redS[4][TS], redQ[4][TS];
    __shared__ float s_mean[TS], s_rstd[TS];

    int blk = blockIdx.x;
    int b = blk >> 9, t8 = blk & 511;
    int tid = threadIdx.x;
    int s0 = t8*TS;

    // G0: x tile -> As[r][k] via cp.async
    const float4* xin = reinterpret_cast<const float4*>(x + ((size_t)(b*Sq + s0))*LNE);
    #pragma unroll
    for(int q=0;q<8;q++){
        int i = tid + q*128;
        int lin = i*4;
        int s = lin >> 9, lam = lin & 511, h = lam >> 6, k = lam & 63;
        cp16(su32(&As[(s*8+h)*RK + k]), xin + i);
    }
    cpcommit();
    // G1: W frag chunk 0: 768 float4 contiguous in g_wfrag, 6 per thread
    {
        const float4* wsrc = reinterpret_cast<const float4*>(g_wfrag);
        #pragma unroll
        for(int j=0;j<6;j++){
            int id = tid + j*128;            // 0..767
            int ln = id/24, seg = id%24;
            cp16(su32(Wst[0] + ln*WLS + seg*4), wsrc + id);
        }
    }
    cpcommit();
    cpwait<1>();
    __syncthreads();

    // exclusive cumsum in registers + fused LN stats
    float cs[4][TS];
    float psum[TS], psq[TS];
    #pragma unroll
    for(int s=0;s<TS;s++){ psum[s]=0.f; psq[s]=0.f; }
    #pragma unroll
    for(int q=0;q<4;q++){
        int lam = tid + q*128;
        int h = lam >> 6, k = lam & 63;
        float run = g_toff[((size_t)(b*NT + t8))*LNE + lam];
        #pragma unroll
        for(int s=0;s<TS;s++){
            float xv = As[(s*8+h)*RK + k];
            cs[q][s] = run;
            psum[s] += run;
            psq[s]  += run*run;
            run += xv;
        }
    }
    #pragma unroll
    for(int o=16;o>0;o>>=1){
        #pragma unroll
        for(int s=0;s<TS;s++){
            psum[s] += __shfl_xor_sync(0xffffffffu, psum[s], o);
            psq[s]  += __shfl_xor_sync(0xffffffffu, psq[s],  o);
        }
    }
    {
        int w = tid >> 5, lanei = tid & 31;
        if(lanei==0){
            #pragma unroll
            for(int s=0;s<TS;s++){ redS[w][s] = psum[s]; redQ[w][s] = psq[s]; }
        }
    }
    __syncthreads();
    if(tid < TS){
        float sum = redS[0][tid] + redS[1][tid] + redS[2][tid] + redS[3][tid];
        float sq  = redQ[0][tid] + redQ[1][tid] + redQ[2][tid] + redQ[3][tid];
        float m = sum * (1.f/512.f);
        float var = sq * (1.f/512.f) - m*m;
        s_mean[tid] = m;
        s_rstd[tid] = rsqrtf(var + 1e-5f);
    }
    __syncthreads();

    // write normalized csum -> As[r][64+k]
    #pragma unroll
    for(int q=0;q<4;q++){
        int lam = tid + q*128;
        int h = lam >> 6, k = lam & 63;
        float ga = gamma[lam], be = beta[lam];
        #pragma unroll
        for(int s=0;s<TS;s++){
            As[(s*8+h)*RK + 64 + k] =
                (cs[q][s] - s_mean[s]) * s_rstd[s] * ga + be;
        }
    }

    // ===== tf32 mma mainloop (frag-ordered B via LDS.128) =====
    int lane = tid & 31, wq = tid >> 5;
    int g = lane >> 2, t = lane & 3;
    int rb = wq*16;
    float acc[24][4];
    #pragma unroll
    for(int nt=0;nt<24;nt++)
        #pragma unroll
        for(int e=0;e<4;e++) acc[nt][e] = 0.f;

    for(int c=0;c<W1N;c++){
        cpwait<0>();
        __syncthreads();
        if(c+1 < W1N){
            const float4* wsrc = reinterpret_cast<const float4*>(
                g_wfrag + (size_t)(c+1)*32*96);
            float* dst = Wst[(c+1)&1];
            #pragma unroll
            for(int j=0;j<6;j++){
                int id = tid + j*128;
                int ln = id/24, seg = id%24;
                cp16(su32(dst + ln*WLS + seg*4), wsrc + id);
            }
        }
        cpcommit();

        int k0 = c*8;
        // A fragments (hi/lo split at load)
        float ar[4];
        ar[0] = As[(rb+g  )*RK + k0 + t    ];
        ar[1] = As[(rb+g+8)*RK + k0 + t    ];
        ar[2] = As[(rb+g  )*RK + k0 + t + 4];
        ar[3] = As[(rb+g+8)*RK + k0 + t + 4];
        unsigned ah[4], al[4];
        #pragma unroll
        for(int e=0;e<4;e++){
            ah[e] = tf32r(ar[e]);
            al[e] = tf32r(ar[e] - __uint_as_float(ah[e]));
        }

        const float* wf = Wst[c&1] + lane*WLS;
        #pragma unroll
        for(int ntg=0;ntg<6;ntg++){
            float4 h0 = *reinterpret_cast<const float4*>(wf + ntg*8);       // nt=4g..+1
            float4 h1 = *reinterpret_cast<const float4*>(wf + ntg*8 + 4);   // nt=+2,+3
            float4 l0 = *reinterpret_cast<const float4*>(wf + 48 + ntg*8);
            float4 l1 = *reinterpret_cast<const float4*>(wf + 48 + ntg*8 + 4);
            int n0 = ntg*4;
            mma8(acc[n0+0], ah, __float_as_uint(h0.x), __float_as_uint(h0.y));
            mma8(acc[n0+0], ah, __float_as_uint(l0.x), __float_as_uint(l0.y));
            mma8(acc[n0+0], al, __float_as_uint(h0.x), __float_as_uint(h0.y));
            mma8(acc[n0+1], ah, __float_as_uint(h0.z), __float_as_uint(h0.w));
            mma8(acc[n0+1], ah, __float_as_uint(l0.z), __float_as_uint(l0.w));
            mma8(acc[n0+1], al, __float_as_uint(h0.z), __float_as_uint(h0.w));
            mma8(acc[n0+2], ah, __float_as_uint(h1.x), __float_as_uint(h1.y));
            mma8(acc[n0+2], ah, __float_as_uint(l1.x), __float_as_uint(l1.y));
            mma8(acc[n0+2], al, __float_as_uint(h1.x), __float_as_uint(h1.y));
            mma8(acc[n0+3], ah, __float_as_uint(h1.z), __float_as_uint(h1.w));
            mma8(acc[n0+3], ah, __float_as_uint(l1.z), __float_as_uint(l1.w));
            mma8(acc[n0+3], al, __float_as_uint(h1.z), __float_as_uint(h1.w));
        }
    }
    __syncthreads();   // done with As; smem becomes Fs|Is

    float* Fs = smem;            // [64][FS]
    float* Is = smem + 64*FS;

    // gates: thread owns rows {rb+g, rb+g+8}, cols {8nt+2t, +1}; triples via nt/nt+8/nt+16
    #pragma unroll
    for(int nt=0;nt<8;nt++){
        int j = nt*8 + 2*t;
        float2 bi  = *reinterpret_cast<const float2*>(&bh[j]);
        float2 bf  = *reinterpret_cast<const float2*>(&bh[64+j]);
        float2 bhd = *reinterpret_cast<const float2*>(&bh[128+j]);
        #pragma unroll
        for(int half=0;half<2;half++){
            int r = rb + g + half*8;
            int s = r >> 3, h = r & 7;
            float ig0 = acc[nt   ][half*2+0] + bi.x;
            float ig1 = acc[nt   ][half*2+1] + bi.y;
            float fr0 = acc[nt+8 ][half*2+0] + bf.x;
            float fr1 = acc[nt+8 ][half*2+1] + bf.y;
            float hd0 = acc[nt+16][half*2+0] + bhd.x;
            float hd1 = acc[nt+16][half*2+1] + bhd.y;
            float f0 = sigm(fr0), f1 = sigm(fr1);
            float g0 = sigm(ig0)*fmaxf(hd0,0.f);
            float g1 = sigm(ig1)*fmaxf(hd1,0.f);
            size_t gi = ((size_t)(b*Sq + s0 + s))*LNE + h*64 + j;
            *reinterpret_cast<float2*>(&g_fg [gi]) = make_float2(f0,f1);
            *reinterpret_cast<float2*>(&g_igh[gi]) = make_float2(g0,g1);
            *reinterpret_cast<float2*>(&Fs[r*FS + j]) = make_float2(f0,f1);
            *reinterpret_cast<float2*>(&Is[r*FS + j]) = make_float2(g0,g1);
        }
    }
    __syncthreads();

    // per-tile lgate partials
    #pragma unroll
    for(int q=0;q<4;q++){
        int lam = tid + q*128;
        int h = lam >> 6, d = lam & 63;
        float A = 1.f, Bv = 0.f;
        #pragma unroll
        for(int s=0;s<TS;s++){
            int r = s*8 + h;
            float f = Fs[r*FS + d];
            float v = Is[r*FS + d];
            Bv = Bv*f + v;
            A *= f;
        }
        size_t ti = ((size_t)(b*NT + t8))*LNE + lam;
        g_tA[ti] = A;
        g_tB[ti] = Bv;
    }
}

// ============ cell carry scan over tiles ============
__global__ void k_cgsum(){
    int blk = blockIdx.x;
    int b = blk >> 4, g = blk & 15;
    int lane = threadIdx.x;
    size_t base = ((size_t)b*NT + g*GT)*LNE + lane;
    float A = 1.f, Bv = 0.f;
    #pragma unroll
    for(int i=0;i<GT;i++){
        float a = g_tA[base + (size_t)i*LNE];
        float v = g_tB[base + (size_t)i*LNE];
        Bv = Bv*a + v;
        A *= a;
    }
    g_gA[(size_t)blk*LNE + lane] = A;
    g_gB[(size_t)blk*LNE + lane] = Bv;
}

__global__ void k_ctscan(const float* __restrict__ icx){
    int blk = blockIdx.x;
    int b = blk >> 4, g = blk & 15;
    int lane = threadIdx.x;
    float c = icx[lane];
    size_t gbase = ((size_t)b*GN)*LNE + lane;
    for(int i=0;i<g;i++)
        c = g_gA[gbase + (size_t)i*LNE]*c + g_gB[gbase + (size_t)i*LNE];
    size_t base = ((size_t)b*NT + g*GT)*LNE + lane;
    #pragma unroll
    for(int i=0;i<GT;i++){
        g_cIn[base + (size_t)i*LNE] = c;
        c = g_tA[base + (size_t)i*LNE]*c + g_tB[base + (size_t)i*LNE];
    }
}

// ============ GEMM2 (og) + cell recompute + output (FFMA2) ============
#define W2C 16
#define W2N 8
__global__ __launch_bounds__(128, 2) void k_gemm2(
    const float* __restrict__ x, const float* __restrict__ Wo,
    const float* __restrict__ bo, float* __restrict__ out)
{
    __shared__ __align__(16) float As[64*RK];
    __shared__ __align__(16) float Wb[2][W2C*64];
    int blk = blockIdx.x;
    int b = blk >> 9, t = blk & 511;
    int tid = threadIdx.x;
    int s0 = t*TS;

    const float4* xin = reinterpret_cast<const float4*>(x + ((size_t)(b*Sq + s0))*LNE);
    #pragma unroll
    for(int q=0;q<8;q++){
        int i = tid + q*128;
        int lin = i*4;
        int s = lin >> 9, lam = lin & 511, h = lam >> 6, k = lam & 63;
        cp16(su32(&As[(s*8+h)*RK + k]), xin + i);
    }
    cpcommit();
    {
        const float4* wsrc = reinterpret_cast<const float4*>(Wo);
        cp16(su32(&Wb[0][tid*4]), wsrc + tid);
        cp16(su32(&Wb[0][(tid+128)*4]), wsrc + tid + 128);
    }
    cpcommit();

    #pragma unroll
    for(int q=0;q<4;q++){
        int lam = tid + q*128;
        int h = lam >> 6, k = lam & 63;
        float c = g_cIn[((size_t)(b*NT + t))*LNE + lam];
        size_t idx = ((size_t)(b*Sq + s0))*LNE + lam;
        #pragma unroll
        for(int s=0;s<TS;s++){
            c = g_fg[idx]*c + g_igh[idx];
            As[(s*8+h)*RK + 64 + k] = c;
            idx += LNE;
        }
    }

    int tx = tid & 15, ty = tid >> 4;
    int r0 = ty*8, c0 = tx*4;
    unsigned long long acc[8][2];
    #pragma unroll
    for(int i=0;i<8;i++){ acc[i][0]=0ull; acc[i][1]=0ull; }

    for(int c=0;c<W2N;c++){
        cpwait<0>();
        __syncthreads();
        if(c+1 < W2N){
            const float4* wsrc = reinterpret_cast<const float4*>(Wo + (c+1)*W2C*64);
            float* dst = Wb[(c+1)&1];
            cp16(su32(dst + tid*4), wsrc + tid);
            cp16(su32(dst + (tid+128)*4), wsrc + tid + 128);
        }
        cpcommit();

        const float* wc = Wb[c&1];
        #pragma unroll
        for(int kq=0;kq<W2C/4;kq++){
            int kl0 = kq*4;
            float4 av[8];
            #pragma unroll
            for(int i=0;i<8;i++)
                av[i] = *reinterpret_cast<const float4*>(&As[(r0+i)*RK + c*W2C + kl0]);
            #pragma unroll
            for(int kk=0;kk<4;kk++){
                int kl = kl0 + kk;
                ulonglong2 w = *reinterpret_cast<const ulonglong2*>(wc + kl*64 + c0);
                unsigned long long aa[8];
                #pragma unroll
                for(int i=0;i<8;i++){
                    float a = (kk==0)?av[i].x:(kk==1)?av[i].y:(kk==2)?av[i].z:av[i].w;
                    aa[i] = pk2(a, a);
                }
                #pragma unroll
                for(int i=0;i<8;i++){
                    fma2(acc[i][0], aa[i], w.x); fma2(acc[i][1], aa[i], w.y);
                }
            }
        }
    }

    float bo4[4];
    #pragma unroll
    for(int j=0;j<4;j++) bo4[j] = bo[c0+j];

    #pragma unroll
    for(int i=0;i<8;i++){
        int r = r0 + i, s = r >> 3, h = r & 7;
        float2 v0 = up2(acc[i][0]), v1 = up2(acc[i][1]);
        float o0 = sigm(v0.x + bo4[0]);
        float o1 = sigm(v0.y + bo4[1]);
        float o2 = sigm(v1.x + bo4[2]);
        float o3 = sigm(v1.y + bo4[3]);
        float4 cv = *reinterpret_cast<const float4*>(&As[r*RK + 64 + c0]);
        float* dst = out + (((size_t)(b*Sq + s0 + s)*Hn + h)*64) + c0;
        *reinterpret_cast<float4*>(dst) =
            make_float4(o0*cv.x, o1*cv.y, o2*cv.z, o3*cv.w);
    }
}

extern "C" void kernel_launch(void* const* d_in, const int* in_sizes, int n_in,
                              void* d_out, int out_size)
{
    const float* x     = (const float*)d_in[0];
    const float* Wh    = (const float*)d_in[1];
    const float* bh    = (const float*)d_in[2];
    const float* Wo    = (const float*)d_in[3];
    const float* bo    = (const float*)d_in[4];
    const float* gamma = (const float*)d_in[5];
    const float* beta  = (const float*)d_in[6];
    const float* icx   = (const float*)d_in[7];
    float* out = (float*)d_out;

    cudaFuncSetAttribute(k_ln_gemm1,
        cudaFuncAttributeMaxDynamicSharedMemorySize, SB_BYTES);

    k_wsplit  <<<24, 512>>>(Wh);
    k_tilesum <<<Bz*NT, 512>>>(x);
    k_gsum    <<<Bz*GN, 512>>>();
    k_tscan   <<<Bz*GN, 512>>>();
    k_ln_gemm1<<<Bz*NT, 128, SB_BYTES>>>(x, bh, gamma, beta);
    k_cgsum   <<<Bz*GN, 512>>>();
    k_ctscan  <<<Bz*GN, 512>>>(icx);
    k_gemm2   <<<Bz*NT, 128>>>(x, Wo, bo, out);
}